// round 2
// baseline (speedup 1.0000x reference)
#include <cuda_runtime.h>
#include <math.h>

#define N_   256
#define FB_  256
#define D_   64
#define H_   4
#define DH_  128
#define HD_  512   // H*DH
#define BD_  128
#define HBD_ 512   // H*BD
#define AK_  100
#define L_   4
#define EPS_ 1e-5f

// ---------------- scratch (device globals; no allocations) ----------------
__device__ float g_d[N_ * N_];
__device__ int   g_pairCount;
__device__ int   g_pairList[N_ * N_];
__device__ float g_diffs[L_ * H_ * N_ * N_];   // 4 MB
__device__ float g_cdiffs[L_ * H_];
__device__ float g_q[N_ * D_];
__device__ float g_k[N_ * D_];
__device__ float g_pred[2][N_];
__device__ float g_pq[N_ * HD_];
__device__ float g_pk[N_ * HD_];
__device__ float g_pkT[HD_ * N_];
__device__ float g_vals[H_ * N_];

__device__ __forceinline__ float mishf(float x) {
    float sp = (x > 20.f) ? x : log1pf(expf(x));
    return x * tanhf(sp);
}

// ---------------- K_reset ----------------
__global__ void k_reset() { g_pairCount = 0; }

// ---------------- K0: node embedding + initial predictions ----------------
__global__ void k_init(const float* __restrict__ X, const float* __restrict__ embW,
                       const float* __restrict__ embB, const float* __restrict__ boutW,
                       const float* __restrict__ boutB) {
    __shared__ float sx[FB_];
    __shared__ float red[64];
    int i = blockIdx.x, c = threadIdx.x;                 // 64 threads
    for (int f = c; f < FB_; f += 64) sx[f] = X[i * FB_ + f];
    __syncthreads();
    float acc = 0.f;
    for (int f = 0; f < FB_; f++) acc += sx[f] * embW[f * D_ + c];
    acc += embB[c];
    g_q[i * D_ + c] = acc;
    g_k[i * D_ + c] = acc;
    float pacc = 0.f;
    for (int f = c; f < FB_; f += 64) pacc += sx[f] * boutW[f];
    red[c] = pacc;
    __syncthreads();
    for (int s = 32; s > 0; s >>= 1) {
        if (c < s) red[c] += red[c + s];
        __syncthreads();
    }
    if (c == 0) g_pred[0][i] = red[0] + boutB[0];
}

// ---------------- K1: pairwise distances + active-pair classification ----------------
__global__ void k_dist(const float* __restrict__ E) {
    __shared__ float se[AK_];
    int i = blockIdx.x, j = threadIdx.x;                 // 256 threads
    for (int a = j; a < AK_; a += 256) se[a] = E[i * AK_ + a];
    __syncthreads();
    float sq = 0.f;
    for (int a = 0; a < AK_; a++) { float t = se[a] - E[j * AK_ + a]; sq += t * t; }
    float dd = (sq > 0.f) ? sqrtf(sq) : 0.f;
    g_d[i * N_ + j] = dd;
    // d > 2.0 => every RBF term exp(< -127) == exactly 0.0f in fp32 (same as reference)
    if (dd <= 2.0f) {
        int p = atomicAdd(&g_pairCount, 1);
        g_pairList[p] = i * N_ + j;
    }
}

// ---------------- K2a: constant-path diffs (zero-bias pipeline) ----------------
__global__ void k_cdiffs(const float* __restrict__ bpW, const float* __restrict__ bpB,
                         const float* __restrict__ bowW, const float* __restrict__ bowB) {
    __shared__ float beta[BD_];
    __shared__ float b[HBD_];
    int tid = threadIdx.x;                                // 512 threads
    if (tid < BD_) beta[tid] = 0.f;
    __syncthreads();
    for (int l = 0; l < L_; l++) {
        const float* W = bpW + l * BD_ * HBD_;
        float acc = 0.f;
        for (int c = 0; c < BD_; c++) acc += beta[c] * W[c * HBD_ + tid];
        b[tid] = acc + bpB[l * HBD_ + tid];
        __syncthreads();
        if (tid < H_) {
            float s = 0.f;
            for (int bd = 0; bd < BD_; bd++) { float v = b[tid * BD_ + bd]; s += v * v; }
            g_cdiffs[l * H_ + tid] = sqrtf(s);
        }
        if (l < L_ - 1 && tid < BD_) {
            const float* W2 = bowW + l * HBD_ * BD_;
            float a2 = 0.f;
            for (int o = 0; o < HBD_; o++) a2 += b[o] * W2[o * BD_ + tid];
            a2 += bowB[l * BD_ + tid];
            __syncthreads();
            beta[tid] = mishf(a2);
        } else {
            __syncthreads();
        }
        __syncthreads();
    }
}

// ---------------- K2b: broadcast-fill diffs with constants ----------------
__global__ void k_fill() {
    int total = L_ * H_ * N_ * N_;
    for (int idx = blockIdx.x * blockDim.x + threadIdx.x; idx < total;
         idx += gridDim.x * blockDim.x)
        g_diffs[idx] = g_cdiffs[idx >> 16];
}

// ---------------- K3: full bias pipeline for active pairs ----------------
__global__ void k_active(const float* __restrict__ bpW, const float* __restrict__ bpB,
                         const float* __restrict__ bowW, const float* __restrict__ bowB) {
    __shared__ float beta[8][BD_];
    __shared__ float sb[8][HBD_];
    __shared__ int   si[8], sj[8];
    __shared__ float sd[8];
    int tid = threadIdx.x;                                // 512 threads
    int count = g_pairCount;
    int nChunks = (count + 7) >> 3;
    for (int ch = blockIdx.x; ch < nChunks; ch += gridDim.x) {
        int pbase = ch << 3;
        int np = count - pbase; if (np > 8) np = 8;
        if (tid < 8) {
            if (tid < np) {
                int pr = g_pairList[pbase + tid];
                si[tid] = pr >> 8; sj[tid] = pr & 255; sd[tid] = g_d[pr];
            } else { si[tid] = 0; sj[tid] = 0; sd[tid] = 1e9f; }
        }
        __syncthreads();
        for (int idx = tid; idx < 8 * BD_; idx += 512) {
            int p = idx >> 7, c = idx & 127;
            float dd = sd[p] - (float)c * (1.0f / 127.0f);
            beta[p][c] = (p < np) ? expf(-127.0f * dd * dd) : 0.f;
        }
        __syncthreads();
        for (int l = 0; l < L_; l++) {
            const float* W = bpW + l * BD_ * HBD_;
            float acc[8];
#pragma unroll
            for (int p = 0; p < 8; p++) acc[p] = 0.f;
            for (int c = 0; c < BD_; c++) {
                float w = W[c * HBD_ + tid];
#pragma unroll
                for (int p = 0; p < 8; p++) acc[p] += beta[p][c] * w;
            }
            float bb = bpB[l * HBD_ + tid];
#pragma unroll
            for (int p = 0; p < 8; p++) sb[p][tid] = acc[p] + bb;
            __syncthreads();
            if (tid < 32) {
                int p = tid >> 2, h = tid & 3;
                if (p < np) {
                    float s = 0.f;
                    for (int bd = 0; bd < BD_; bd++) { float v = sb[p][h * BD_ + bd]; s += v * v; }
                    g_diffs[((l * H_ + h) * N_ + si[p]) * N_ + sj[p]] = sqrtf(s);
                }
            }
            if (l < L_ - 1) {
                int c = tid & 127, g = tid >> 7;          // g in 0..3
                const float* W2 = bowW + l * HBD_ * BD_;
                float a0 = 0.f, a1 = 0.f;
                for (int o = 0; o < HBD_; o++) {
                    float w = W2[o * BD_ + c];
                    a0 += sb[g][o] * w;
                    a1 += sb[g + 4][o] * w;
                }
                float bb2 = bowB[l * BD_ + c];
                beta[g][c]     = mishf(a0 + bb2);
                beta[g + 4][c] = mishf(a1 + bb2);
            }
            __syncthreads();
        }
        __syncthreads();
    }
}

// ---------------- K4: q/k projections (per layer) ----------------
__global__ void k_proj(const float* __restrict__ qpW, const float* __restrict__ qpB,
                       const float* __restrict__ kpW, const float* __restrict__ kpB, int l) {
    __shared__ float sx[16][D_];
    int b = blockIdx.x, tid = threadIdx.x;                // 512 threads
    bool isK = (b >= 16);
    int r0 = (b & 15) * 16;
    const float* src = isK ? g_k : g_q;
    const float* W  = (isK ? kpW : qpW) + l * D_ * HD_;
    const float* Bi = (isK ? kpB : qpB) + l * HD_;
    for (int idx = tid; idx < 16 * D_; idx += 512)
        sx[idx / D_][idx % D_] = src[(r0 + idx / D_) * D_ + (idx % D_)];
    __syncthreads();
    float acc[16];
#pragma unroll
    for (int r = 0; r < 16; r++) acc[r] = 0.f;
    for (int c = 0; c < D_; c++) {
        float w = W[c * HD_ + tid];
#pragma unroll
        for (int r = 0; r < 16; r++) acc[r] += sx[r][c] * w;
    }
    float bb = Bi[tid];
#pragma unroll
    for (int r = 0; r < 16; r++) {
        float v = acc[r] + bb;
        if (isK) {
            g_pk[(r0 + r) * HD_ + tid] = v;
            g_pkT[tid * N_ + r0 + r]   = v;
        } else {
            g_pq[(r0 + r) * HD_ + tid] = v;
        }
    }
}

// ---------------- K5: attention per (head, 8-row i tile) ----------------
__global__ void k_attn(const float* __restrict__ nt, int l) {
    __shared__ float pqs[8][DH_];
    __shared__ float red[8][256];
    __shared__ float ssum[8];
    int tid = threadIdx.x;                                // 256 threads
    int h = blockIdx.x & 3, i0 = (blockIdx.x >> 2) * 8;
    for (int idx = tid; idx < 8 * DH_; idx += 256) {
        int ii = idx >> 7, dd = idx & 127;
        pqs[ii][dd] = g_pq[(i0 + ii) * HD_ + h * DH_ + dd];
    }
    __syncthreads();
    int j = tid;
    float acc[8];
#pragma unroll
    for (int ii = 0; ii < 8; ii++) acc[ii] = 0.f;
    const float* pkt = g_pkT + h * DH_ * N_;
    for (int dd = 0; dd < DH_; dd++) {
        float pkv = pkt[dd * N_ + j];
#pragma unroll
        for (int ii = 0; ii < 8; ii++) acc[ii] += pqs[ii][dd] * pkv;
    }
    const float scale = 0.0883883476483184f;              // 1/sqrt(128)
    const float* dptr = g_diffs + (l * H_ + h) * N_ * N_;
#pragma unroll
    for (int ii = 0; ii < 8; ii++)
        acc[ii] = acc[ii] * scale + dptr[(i0 + ii) * N_ + j];
    // max reduce
#pragma unroll
    for (int ii = 0; ii < 8; ii++) red[ii][tid] = acc[ii];
    __syncthreads();
    for (int s = 128; s > 0; s >>= 1) {
        if (tid < s) {
#pragma unroll
            for (int ii = 0; ii < 8; ii++)
                red[ii][tid] = fmaxf(red[ii][tid], red[ii][tid + s]);
        }
        __syncthreads();
    }
    float mx[8], e[8];
#pragma unroll
    for (int ii = 0; ii < 8; ii++) mx[ii] = red[ii][0];
    __syncthreads();
#pragma unroll
    for (int ii = 0; ii < 8; ii++) e[ii] = expf(acc[ii] - mx[ii]);
    // sum reduce
#pragma unroll
    for (int ii = 0; ii < 8; ii++) red[ii][tid] = e[ii];
    __syncthreads();
    for (int s = 128; s > 0; s >>= 1) {
        if (tid < s) {
#pragma unroll
            for (int ii = 0; ii < 8; ii++) red[ii][tid] += red[ii][tid + s];
        }
        __syncthreads();
    }
    if (tid < 8) ssum[tid] = red[tid][0];
    __syncthreads();
    // weighted-value reduce (value depends on target row i)
    const float* predOld = g_pred[l & 1];
    float ntj = nt[j];
#pragma unroll
    for (int ii = 0; ii < 8; ii++) {
        float v = (j == i0 + ii) ? predOld[i0 + ii] : ntj;
        red[ii][tid] = e[ii] * v;
    }
    __syncthreads();
    for (int s = 128; s > 0; s >>= 1) {
        if (tid < s) {
#pragma unroll
            for (int ii = 0; ii < 8; ii++) red[ii][tid] += red[ii][tid + s];
        }
        __syncthreads();
    }
    if (tid < 8) g_vals[h * N_ + i0 + tid] = red[tid][0] / ssum[tid];
}

// ---------------- K5b: predictions = mean over heads ----------------
__global__ void k_predup(int l) {
    int i = threadIdx.x;                                  // 256 threads
    float s = 0.f;
#pragma unroll
    for (int h = 0; h < H_; h++) s += g_vals[h * N_ + i];
    g_pred[(l + 1) & 1][i] = 0.25f * s;
}

// ---------------- K6: residual + mish + LayerNorm for q and k ----------------
__global__ void k_update(const float* __restrict__ qoW, const float* __restrict__ qoB,
                         const float* __restrict__ koW, const float* __restrict__ koB,
                         const float* __restrict__ qlnG, const float* __restrict__ qlnB,
                         const float* __restrict__ klnG, const float* __restrict__ klnB, int l) {
    __shared__ float sp[8][HD_];                          // 16 KB
    __shared__ float srs[8][64];
    __shared__ float srq[8][64];
    int tid = threadIdx.x;                                // 512 threads
    bool isK = (blockIdx.x >= 32);
    int r0 = (blockIdx.x & 31) * 8;
    const float* P  = isK ? g_pk : g_pq;
    const float* W  = (isK ? koW : qoW) + l * HD_ * D_;
    const float* Bi = (isK ? koB : qoB) + l * D_;
    const float* G  = (isK ? klnG : qlnG) + l * D_;
    const float* Bt = (isK ? klnB : qlnB) + l * D_;
    float* dst = isK ? g_k : g_q;
    for (int idx = tid; idx < 8 * HD_; idx += 512)
        sp[idx >> 9][idx & 511] = P[(r0 + (idx >> 9)) * HD_ + (idx & 511)];
    __syncthreads();
    int r = tid >> 6, c = tid & 63;
    float acc = 0.f;
    for (int m = 0; m < HD_; m++) {
        float pv = sp[r][(m & 3) * DH_ + (m >> 2)];       // pq_flat[m] = pq[(m%H)*DH + m/H]
        acc += pv * W[m * D_ + c];
    }
    float y = dst[(r0 + r) * D_ + c] + mishf(acc + Bi[c]);
    srs[r][c] = y;
    srq[r][c] = y * y;
    __syncthreads();
    for (int s = 32; s > 0; s >>= 1) {
        if (c < s) { srs[r][c] += srs[r][c + s]; srq[r][c] += srq[r][c + s]; }
        __syncthreads();
    }
    float mean = srs[r][0] * (1.0f / 64.0f);
    float var  = srq[r][0] * (1.0f / 64.0f) - mean * mean;
    float out  = (y - mean) * rsqrtf(var + EPS_) * G[c] + Bt[c];
    dst[(r0 + r) * D_ + c] = out;
}

// ---------------- K_out ----------------
__global__ void k_out(float* __restrict__ out) {
    int i = threadIdx.x;
    out[i] = g_pred[L_ & 1][i];                           // L even -> buffer 0
}

// ---------------- launch ----------------
extern "C" void kernel_launch(void* const* d_in, const int* in_sizes, int n_in,
                              void* d_out, int out_size) {
    const float* X     = (const float*)d_in[0];
    const float* E     = (const float*)d_in[1];
    const float* nt    = (const float*)d_in[2];
    const float* embW  = (const float*)d_in[3];
    const float* embB  = (const float*)d_in[4];
    const float* boutW = (const float*)d_in[5];
    const float* boutB = (const float*)d_in[6];
    const float* qpW   = (const float*)d_in[7];
    const float* qpB   = (const float*)d_in[8];
    const float* kpW   = (const float*)d_in[9];
    const float* kpB   = (const float*)d_in[10];
    const float* qoW   = (const float*)d_in[11];
    const float* qoB   = (const float*)d_in[12];
    const float* koW   = (const float*)d_in[13];
    const float* koB   = (const float*)d_in[14];
    const float* bpW   = (const float*)d_in[15];
    const float* bpB   = (const float*)d_in[16];
    const float* bowW  = (const float*)d_in[17];
    const float* bowB  = (const float*)d_in[18];
    const float* qlnG  = (const float*)d_in[19];
    const float* qlnB  = (const float*)d_in[20];
    const float* klnG  = (const float*)d_in[21];
    const float* klnB  = (const float*)d_in[22];

    k_reset<<<1, 1>>>();
    k_init<<<N_, 64>>>(X, embW, embB, boutW, boutB);
    k_dist<<<N_, 256>>>(E);
    k_cdiffs<<<1, 512>>>(bpW, bpB, bowW, bowB);
    k_fill<<<2048, 256>>>();
    k_active<<<32, 512>>>(bpW, bpB, bowW, bowB);
    for (int l = 0; l < L_; l++) {
        k_proj<<<32, 512>>>(qpW, qpB, kpW, kpB, l);
        k_attn<<<128, 256>>>(nt, l);
        k_predup<<<1, 256>>>(l);
        k_update<<<64, 512>>>(qoW, qoB, koW, koB, qlnG, qlnB, klnG, klnB, l);
    }
    k_out<<<1, 256>>>((float*)d_out);
}

// round 3
// speedup vs baseline: 1.4783x; 1.4783x over previous
#include <cuda_runtime.h>
#include <math.h>

#define N_   256
#define FB_  256
#define D_   64
#define H_   4
#define DH_  128
#define HD_  512   // H*DH
#define BD_  128
#define HBD_ 512   // H*BD
#define AK_  100
#define L_   4
#define EPS_ 1e-5f

// ---------------- scratch (device globals; no allocations) ----------------
__device__ float g_d[N_ * N_];
__device__ unsigned char g_act[N_ * N_];
__device__ int   g_pairCount;
__device__ int   g_pairList[N_ * N_];
__device__ float g_diffs[L_ * H_ * N_ * N_];   // only active entries written/read
__device__ float g_cdiffs[L_ * H_];
__device__ float g_ET[AK_ * N_];
__device__ float g_q[N_ * D_];
__device__ float g_k[N_ * D_];
__device__ float g_pred0[N_];
__device__ float g_pq[N_ * HD_];
__device__ float g_pk[N_ * HD_];
__device__ float g_pkT[HD_ * N_];
__device__ float g_vals[2][H_][N_];

__device__ __forceinline__ float mishf(float x) {
    float sp = (x > 20.f) ? x : log1pf(expf(x));
    return x * tanhf(sp);
}

// ---------------- K0: node embedding + initial predictions + E transpose ----------------
__global__ void k_init(const float* __restrict__ X, const float* __restrict__ E,
                       const float* __restrict__ embW, const float* __restrict__ embB,
                       const float* __restrict__ boutW, const float* __restrict__ boutB) {
    __shared__ float sx[FB_];
    __shared__ float red[64];
    int i = blockIdx.x, c = threadIdx.x;                 // 64 threads
    if (i == 0 && c == 0) g_pairCount = 0;
    for (int f = c; f < FB_; f += 64) sx[f] = X[i * FB_ + f];
    for (int a = c; a < AK_; a += 64) g_ET[a * N_ + i] = E[i * AK_ + a];
    __syncthreads();
    float acc = 0.f;
    for (int f = 0; f < FB_; f++) acc += sx[f] * embW[f * D_ + c];
    acc += embB[c];
    g_q[i * D_ + c] = acc;
    g_k[i * D_ + c] = acc;
    float pacc = 0.f;
    for (int f = c; f < FB_; f += 64) pacc += sx[f] * boutW[f];
    red[c] = pacc;
    __syncthreads();
    for (int s = 32; s > 0; s >>= 1) {
        if (c < s) red[c] += red[c + s];
        __syncthreads();
    }
    if (c == 0) g_pred0[i] = red[0] + boutB[0];
}

// ---------------- K1: pairwise distances + active-pair classification ----------------
__global__ void k_dist(const float* __restrict__ E) {
    __shared__ float se[AK_];
    int i = blockIdx.x, j = threadIdx.x;                 // 256 threads
    for (int a = j; a < AK_; a += 256) se[a] = E[i * AK_ + a];
    __syncthreads();
    float sq = 0.f;
    for (int a = 0; a < AK_; a++) { float t = se[a] - g_ET[a * N_ + j]; sq += t * t; }
    float dd = (sq > 0.f) ? sqrtf(sq) : 0.f;
    g_d[i * N_ + j] = dd;
    // d > 2.0 => every RBF term exp(< -127) == exactly 0.0f in fp32 (same as reference)
    bool act = (dd <= 2.0f);
    g_act[i * N_ + j] = act ? 1 : 0;
    if (act) {
        int p = atomicAdd(&g_pairCount, 1);
        g_pairList[p] = i * N_ + j;
    }
}

// ---------------- K2: bias pipeline. Virtual pair 0 = constant (beta=0) path ----------------
__global__ void k_active(const float* __restrict__ bpW, const float* __restrict__ bpB,
                         const float* __restrict__ bowW, const float* __restrict__ bowB) {
    __shared__ float beta[8][BD_];
    __shared__ float sb[8][HBD_];
    __shared__ int   svp[8];
    __shared__ float sd[8];
    int tid = threadIdx.x;                                // 512 threads
    int total = g_pairCount + 1;                          // +1 constant pseudo-pair
    int nChunks = (total + 7) >> 3;
    for (int ch = blockIdx.x; ch < nChunks; ch += gridDim.x) {
        int pbase = ch << 3;
        int np = total - pbase; if (np > 8) np = 8;
        if (tid < 8) {
            int vp = pbase + tid;
            if (tid < np) {
                if (vp == 0) { svp[tid] = -1; sd[tid] = 0.f; }          // constant path
                else { int pr = g_pairList[vp - 1]; svp[tid] = pr; sd[tid] = g_d[pr]; }
            } else { svp[tid] = -2; sd[tid] = 0.f; }
        }
        __syncthreads();
        for (int idx = tid; idx < 8 * BD_; idx += 512) {
            int p = idx >> 7, c = idx & 127;
            float ddv = sd[p] - (float)c * (1.0f / 127.0f);
            beta[p][c] = (p < np && svp[p] >= 0) ? expf(-127.0f * ddv * ddv) : 0.f;
        }
        __syncthreads();
        for (int l = 0; l < L_; l++) {
            const float* W = bpW + l * BD_ * HBD_;
            float acc[8];
#pragma unroll
            for (int p = 0; p < 8; p++) acc[p] = 0.f;
            for (int c = 0; c < BD_; c++) {
                float w = W[c * HBD_ + tid];
#pragma unroll
                for (int p = 0; p < 8; p++) acc[p] += beta[p][c] * w;
            }
            float bb = bpB[l * HBD_ + tid];
#pragma unroll
            for (int p = 0; p < 8; p++) sb[p][tid] = acc[p] + bb;
            __syncthreads();
            if (tid < 32) {
                int p = tid >> 2, h = tid & 3;
                if (p < np && svp[p] != -2) {
                    float s = 0.f;
                    for (int bd = 0; bd < BD_; bd++) { float v = sb[p][h * BD_ + bd]; s += v * v; }
                    float r = sqrtf(s);
                    if (svp[p] == -1) g_cdiffs[l * H_ + h] = r;
                    else              g_diffs[(l * H_ + h) * (N_ * N_) + svp[p]] = r;
                }
            }
            if (l < L_ - 1) {
                int c = tid & 127, g = tid >> 7;          // g in 0..3
                const float* W2 = bowW + l * HBD_ * BD_;
                float a0 = 0.f, a1 = 0.f;
                for (int o = 0; o < HBD_; o++) {
                    float w = W2[o * BD_ + c];
                    a0 += sb[g][o] * w;
                    a1 += sb[g + 4][o] * w;
                }
                float bb2 = bowB[l * BD_ + c];
                beta[g][c]     = mishf(a0 + bb2);
                beta[g + 4][c] = mishf(a1 + bb2);
            }
            __syncthreads();
        }
        __syncthreads();
    }
}

// ---------------- K3: q/k projections (per layer) ----------------
__global__ void k_proj(const float* __restrict__ qpW, const float* __restrict__ qpB,
                       const float* __restrict__ kpW, const float* __restrict__ kpB, int l) {
    __shared__ float sx[16][D_];
    int b = blockIdx.x, tid = threadIdx.x;                // 512 threads
    bool isK = (b >= 16);
    int r0 = (b & 15) * 16;
    const float* src = isK ? g_k : g_q;
    const float* W  = (isK ? kpW : qpW) + l * D_ * HD_;
    const float* Bi = (isK ? kpB : qpB) + l * HD_;
    for (int idx = tid; idx < 16 * D_; idx += 512)
        sx[idx / D_][idx % D_] = src[(r0 + idx / D_) * D_ + (idx % D_)];
    __syncthreads();
    float acc[16];
#pragma unroll
    for (int r = 0; r < 16; r++) acc[r] = 0.f;
    for (int c = 0; c < D_; c++) {
        float w = W[c * HD_ + tid];
#pragma unroll
        for (int r = 0; r < 16; r++) acc[r] += sx[r][c] * w;
    }
    float bb = Bi[tid];
#pragma unroll
    for (int r = 0; r < 16; r++) {
        float v = acc[r] + bb;
        if (isK) {
            g_pk[(r0 + r) * HD_ + tid] = v;
            g_pkT[tid * N_ + r0 + r]   = v;
        } else {
            g_pq[(r0 + r) * HD_ + tid] = v;
        }
    }
}

// ---------------- K4: attention per (head, 8-row i tile); warp-shuffle softmax ----------------
__global__ void k_attn(const float* __restrict__ nt, int l) {
    __shared__ float pqs[8][DH_];
    __shared__ float red[8][256];
    int tid = threadIdx.x;                                // 256 threads = 8 warps
    int h = blockIdx.x & 3, i0 = (blockIdx.x >> 2) * 8;
    for (int idx = tid; idx < 8 * DH_; idx += 256)
        pqs[idx >> 7][idx & 127] = g_pq[(i0 + (idx >> 7)) * HD_ + h * DH_ + (idx & 127)];
    __syncthreads();
    int j = tid;
    float acc[8];
#pragma unroll
    for (int ii = 0; ii < 8; ii++) acc[ii] = 0.f;
    const float* pkt = g_pkT + h * DH_ * N_;
    for (int dd = 0; dd < DH_; dd++) {
        float pkv = pkt[dd * N_ + j];
#pragma unroll
        for (int ii = 0; ii < 8; ii++) acc[ii] += pqs[ii][dd] * pkv;
    }
    const float scale = 0.0883883476483184f;              // 1/sqrt(128)
    float cd = g_cdiffs[l * H_ + h];
    const float* dptr = g_diffs + (l * H_ + h) * (N_ * N_);
#pragma unroll
    for (int ii = 0; ii < 8; ii++) {
        int pr = (i0 + ii) * N_ + j;
        float dv = g_act[pr] ? dptr[pr] : cd;
        red[ii][j] = acc[ii] * scale + dv;
    }
    __syncthreads();
    // warp w owns row i0+w
    int w = tid >> 5, lane = tid & 31;
    float a[8];
#pragma unroll
    for (int k = 0; k < 8; k++) a[k] = red[w][k * 32 + lane];
    float mx = a[0];
#pragma unroll
    for (int k = 1; k < 8; k++) mx = fmaxf(mx, a[k]);
#pragma unroll
    for (int s = 16; s > 0; s >>= 1) mx = fmaxf(mx, __shfl_xor_sync(0xFFFFFFFFu, mx, s));
    float e[8], ssum = 0.f;
#pragma unroll
    for (int k = 0; k < 8; k++) { e[k] = expf(a[k] - mx); ssum += e[k]; }
#pragma unroll
    for (int s = 16; s > 0; s >>= 1) ssum += __shfl_xor_sync(0xFFFFFFFFu, ssum, s);
    int i = i0 + w;
    float predPrev;
    if (l == 0) predPrev = g_pred0[i];
    else {
        int pb = (l & 1) ^ 1;
        predPrev = 0.25f * (g_vals[pb][0][i] + g_vals[pb][1][i] +
                            g_vals[pb][2][i] + g_vals[pb][3][i]);
    }
    float vs = 0.f;
#pragma unroll
    for (int k = 0; k < 8; k++) {
        int jj = k * 32 + lane;
        float v = (jj == i) ? predPrev : nt[jj];
        vs += e[k] * v;
    }
#pragma unroll
    for (int s = 16; s > 0; s >>= 1) vs += __shfl_xor_sync(0xFFFFFFFFu, vs, s);
    if (lane == 0) g_vals[l & 1][h][i] = vs / ssum;
}

// ---------------- K5: residual + mish + LayerNorm for q and k ----------------
__global__ void k_update(const float* __restrict__ qoW, const float* __restrict__ qoB,
                         const float* __restrict__ koW, const float* __restrict__ koB,
                         const float* __restrict__ qlnG, const float* __restrict__ qlnB,
                         const float* __restrict__ klnG, const float* __restrict__ klnB, int l) {
    __shared__ float sp[8][HD_];
    __shared__ float srs[8][64];
    __shared__ float srq[8][64];
    int tid = threadIdx.x;                                // 512 threads
    bool isK = (blockIdx.x >= 32);
    int r0 = (blockIdx.x & 31) * 8;
    const float* P  = isK ? g_pk : g_pq;
    const float* W  = (isK ? koW : qoW) + l * HD_ * D_;
    const float* Bi = (isK ? koB : qoB) + l * D_;
    const float* G  = (isK ? klnG : qlnG) + l * D_;
    const float* Bt = (isK ? klnB : qlnB) + l * D_;
    float* dst = isK ? g_k : g_q;
    for (int idx = tid; idx < 8 * HD_; idx += 512)
        sp[idx >> 9][idx & 511] = P[(r0 + (idx >> 9)) * HD_ + (idx & 511)];
    __syncthreads();
    int r = tid >> 6, c = tid & 63;
    float acc = 0.f;
    for (int m = 0; m < HD_; m++) {
        float pv = sp[r][(m & 3) * DH_ + (m >> 2)];       // pq_flat[m] = pq[(m%H)*DH + m/H]
        acc += pv * W[m * D_ + c];
    }
    float y = dst[(r0 + r) * D_ + c] + mishf(acc + Bi[c]);
    srs[r][c] = y;
    srq[r][c] = y * y;
    __syncthreads();
    for (int s = 32; s > 0; s >>= 1) {
        if (c < s) { srs[r][c] += srs[r][c + s]; srq[r][c] += srq[r][c + s]; }
        __syncthreads();
    }
    float mean = srs[r][0] * (1.0f / 64.0f);
    float var  = srq[r][0] * (1.0f / 64.0f) - mean * mean;
    float out  = (y - mean) * rsqrtf(var + EPS_) * G[c] + Bt[c];
    dst[(r0 + r) * D_ + c] = out;
}

// ---------------- K_out: final mean over heads ----------------
__global__ void k_out(float* __restrict__ out) {
    int i = threadIdx.x;                                  // 256 threads
    int pb = (L_ - 1) & 1;
    out[i] = 0.25f * (g_vals[pb][0][i] + g_vals[pb][1][i] +
                      g_vals[pb][2][i] + g_vals[pb][3][i]);
}

// ---------------- launch ----------------
extern "C" void kernel_launch(void* const* d_in, const int* in_sizes, int n_in,
                              void* d_out, int out_size) {
    const float* X     = (const float*)d_in[0];
    const float* E     = (const float*)d_in[1];
    const float* nt    = (const float*)d_in[2];
    const float* embW  = (const float*)d_in[3];
    const float* embB  = (const float*)d_in[4];
    const float* boutW = (const float*)d_in[5];
    const float* boutB = (const float*)d_in[6];
    const float* qpW   = (const float*)d_in[7];
    const float* qpB   = (const float*)d_in[8];
    const float* kpW   = (const float*)d_in[9];
    const float* kpB   = (const float*)d_in[10];
    const float* qoW   = (const float*)d_in[11];
    const float* qoB   = (const float*)d_in[12];
    const float* koW   = (const float*)d_in[13];
    const float* koB   = (const float*)d_in[14];
    const float* bpW   = (const float*)d_in[15];
    const float* bpB   = (const float*)d_in[16];
    const float* bowW  = (const float*)d_in[17];
    const float* bowB  = (const float*)d_in[18];
    const float* qlnG  = (const float*)d_in[19];
    const float* qlnB  = (const float*)d_in[20];
    const float* klnG  = (const float*)d_in[21];
    const float* klnB  = (const float*)d_in[22];

    k_init<<<N_, 64>>>(X, E, embW, embB, boutW, boutB);
    k_dist<<<N_, 256>>>(E);
    k_active<<<64, 512>>>(bpW, bpB, bowW, bowB);
    for (int l = 0; l < L_; l++) {
        k_proj<<<32, 512>>>(qpW, qpB, kpW, kpB, l);
        k_attn<<<128, 256>>>(nt, l);
        if (l < L_ - 1)
            k_update<<<64, 512>>>(qoW, qoB, koW, koB, qlnG, qlnB, klnG, klnB, l);
    }
    k_out<<<1, 256>>>((float*)d_out);
}

// round 4
// speedup vs baseline: 2.0157x; 1.3635x over previous
#include <cuda_runtime.h>
#include <math.h>

#define N_   256
#define FB_  256
#define D_   64
#define H_   4
#define DH_  128
#define HD_  512   // H*DH
#define BD_  128
#define HBD_ 512   // H*BD
#define AK_  100
#define L_   4
#define EPS_ 1e-5f

// ---------------- scratch (device globals; zero-init, no allocations) ----------------
__device__ float g_d[N_ * N_];
__device__ unsigned char g_act[N_ * N_];
__device__ int   g_pairCount;                  // reset by last-layer kernel for next replay
__device__ int   g_pairList[N_ * N_];
__device__ float g_diffs[L_ * H_ * N_ * N_];   // only active entries written/read
__device__ float g_cdiffs[L_ * H_];
__device__ float g_q[N_ * D_];
__device__ float g_k[N_ * D_];
__device__ float g_pred0[N_];
__device__ float g_pq[N_ * HD_];
__device__ float g_pk[N_ * HD_];
__device__ float g_pkT[HD_ * N_];
__device__ float g_vals[2][H_][N_];

__device__ __forceinline__ float mishf(float x) {
    float sp = (x > 20.f) ? x : log1pf(expf(x));
    return x * tanhf(sp);
}

// ---------------- K0: embedding + initial predictions + distances + out zero ----------------
__global__ void k_initdist(const float* __restrict__ X, const float* __restrict__ E,
                           const float* __restrict__ embW, const float* __restrict__ embB,
                           const float* __restrict__ boutW, const float* __restrict__ boutB,
                           float* __restrict__ out) {
    __shared__ float sx[FB_];
    __shared__ float se[AK_];
    __shared__ float red[256];
    __shared__ float wred[8];
    int i = blockIdx.x, t = threadIdx.x;                  // 256 threads
    sx[t] = X[i * FB_ + t];
    if (t < AK_) se[t] = E[i * AK_ + t];
    if (t == 0) out[i] = 0.f;
    __syncthreads();
    // ---- distances: j = t (E rows L1-resident per block) ----
    float sq = 0.f;
    const float* Ej = E + t * AK_;
#pragma unroll 4
    for (int a = 0; a < AK_; a++) { float d = se[a] - Ej[a]; sq += d * d; }
    float dd = (sq > 0.f) ? sqrtf(sq) : 0.f;
    g_d[i * N_ + t] = dd;
    // d > 2 => every RBF term exp(< -127) == exactly 0.0f in fp32 (same as reference)
    bool act = (dd <= 2.0f);
    g_act[i * N_ + t] = act ? 1 : 0;
    if (act) {
        int p = atomicAdd(&g_pairCount, 1);
        g_pairList[p] = i * N_ + t;
    }
    // ---- embedding: col c = t&63, partial over 64 f's ----
    int c = t & 63, part = t >> 6;
    float acc = 0.f;
    const float* wp = embW + (part * 64) * D_ + c;
#pragma unroll 16
    for (int f = 0; f < 64; f++) acc += sx[part * 64 + f] * wp[f * D_];
    red[t] = acc;
    __syncthreads();
    if (t < D_) {
        float v = red[t] + red[t + 64] + red[t + 128] + red[t + 192] + embB[t];
        g_q[i * D_ + t] = v;
        g_k[i * D_ + t] = v;
    }
    __syncthreads();
    // ---- initial prediction: dot(sx, boutW) ----
    float pacc = sx[t] * boutW[t];
#pragma unroll
    for (int s = 16; s > 0; s >>= 1) pacc += __shfl_xor_sync(0xFFFFFFFFu, pacc, s);
    if ((t & 31) == 0) wred[t >> 5] = pacc;
    __syncthreads();
    if (t == 0) {
        float s = 0.f;
#pragma unroll
        for (int w = 0; w < 8; w++) s += wred[w];
        g_pred0[i] = s + boutB[0];
    }
}

// ---------------- K1: bias pipeline. Virtual pair 0 = constant (beta=0) path ----------------
__global__ void k_active(const float* __restrict__ bpW, const float* __restrict__ bpB,
                         const float* __restrict__ bowW, const float* __restrict__ bowB) {
    __shared__ float beta[8][BD_];
    __shared__ float sb[8][HBD_];
    __shared__ int   svp[8];
    __shared__ float sd[8];
    int tid = threadIdx.x;                                // 512 threads
    int total = g_pairCount + 1;                          // +1 constant pseudo-pair
    int nChunks = (total + 7) >> 3;
    for (int ch = blockIdx.x; ch < nChunks; ch += gridDim.x) {
        int pbase = ch << 3;
        int np = total - pbase; if (np > 8) np = 8;
        if (tid < 8) {
            int vp = pbase + tid;
            if (tid < np) {
                if (vp == 0) { svp[tid] = -1; sd[tid] = 0.f; }          // constant path
                else { int pr = g_pairList[vp - 1]; svp[tid] = pr; sd[tid] = g_d[pr]; }
            } else { svp[tid] = -2; sd[tid] = 0.f; }
        }
        __syncthreads();
        for (int idx = tid; idx < 8 * BD_; idx += 512) {
            int p = idx >> 7, c = idx & 127;
            float ddv = sd[p] - (float)c * (1.0f / 127.0f);
            beta[p][c] = (p < np && svp[p] >= 0) ? expf(-127.0f * ddv * ddv) : 0.f;
        }
        __syncthreads();
        for (int l = 0; l < L_; l++) {
            const float* W = bpW + l * BD_ * HBD_;
            float acc[8];
#pragma unroll
            for (int p = 0; p < 8; p++) acc[p] = 0.f;
#pragma unroll 8
            for (int c = 0; c < BD_; c++) {
                float w = W[c * HBD_ + tid];
#pragma unroll
                for (int p = 0; p < 8; p++) acc[p] += beta[p][c] * w;
            }
            float bb = bpB[l * HBD_ + tid];
#pragma unroll
            for (int p = 0; p < 8; p++) sb[p][tid] = acc[p] + bb;
            __syncthreads();
            if (tid < 32) {
                int p = tid >> 2, h = tid & 3;
                if (p < np && svp[p] != -2) {
                    float s = 0.f;
#pragma unroll 8
                    for (int bd = 0; bd < BD_; bd++) { float v = sb[p][h * BD_ + bd]; s += v * v; }
                    float r = sqrtf(s);
                    if (svp[p] == -1) g_cdiffs[l * H_ + h] = r;
                    else              g_diffs[(l * H_ + h) * (N_ * N_) + svp[p]] = r;
                }
            }
            if (l < L_ - 1) {
                int c = tid & 127, g = tid >> 7;          // g in 0..3
                const float* W2 = bowW + l * HBD_ * BD_;
                float a0 = 0.f, a1 = 0.f;
#pragma unroll 8
                for (int o = 0; o < HBD_; o++) {
                    float w = W2[o * BD_ + c];
                    a0 += sb[g][o] * w;
                    a1 += sb[g + 4][o] * w;
                }
                float bb2 = bowB[l * BD_ + c];
                beta[g][c]     = mishf(a0 + bb2);
                beta[g + 4][c] = mishf(a1 + bb2);
            }
            __syncthreads();
        }
        __syncthreads();
    }
}

// ---------------- K2: q/k projections (per layer), 128 blocks x 4 rows ----------------
__global__ void k_proj(const float* __restrict__ qpW, const float* __restrict__ qpB,
                       const float* __restrict__ kpW, const float* __restrict__ kpB, int l) {
    __shared__ float sx[4][D_];
    int b = blockIdx.x, tid = threadIdx.x;                // 512 threads
    bool isK = (b >= 64);
    int r0 = (b & 63) * 4;
    const float* src = isK ? g_k : g_q;
    const float* W  = (isK ? kpW : qpW) + l * D_ * HD_;
    const float* Bi = (isK ? kpB : qpB) + l * HD_;
    if (tid < 4 * D_) sx[tid >> 6][tid & 63] = src[(r0 + (tid >> 6)) * D_ + (tid & 63)];
    __syncthreads();
    float a0 = 0.f, a1 = 0.f, a2 = 0.f, a3 = 0.f;
#pragma unroll 16
    for (int c = 0; c < D_; c++) {
        float w = W[c * HD_ + tid];
        a0 += sx[0][c] * w;
        a1 += sx[1][c] * w;
        a2 += sx[2][c] * w;
        a3 += sx[3][c] * w;
    }
    float bb = Bi[tid];
    a0 += bb; a1 += bb; a2 += bb; a3 += bb;
    if (isK) {
        g_pk[(r0 + 0) * HD_ + tid] = a0;
        g_pk[(r0 + 1) * HD_ + tid] = a1;
        g_pk[(r0 + 2) * HD_ + tid] = a2;
        g_pk[(r0 + 3) * HD_ + tid] = a3;
        g_pkT[tid * N_ + r0 + 0] = a0;
        g_pkT[tid * N_ + r0 + 1] = a1;
        g_pkT[tid * N_ + r0 + 2] = a2;
        g_pkT[tid * N_ + r0 + 3] = a3;
    } else {
        g_pq[(r0 + 0) * HD_ + tid] = a0;
        g_pq[(r0 + 1) * HD_ + tid] = a1;
        g_pq[(r0 + 2) * HD_ + tid] = a2;
        g_pq[(r0 + 3) * HD_ + tid] = a3;
    }
}

// ---------------- K3: fused attention (blocks 0-127) + q/k update (blocks 128-255) ----------
__global__ void k_layer(const float* __restrict__ nt,
                        const float* __restrict__ qoW, const float* __restrict__ qoB,
                        const float* __restrict__ koW, const float* __restrict__ koB,
                        const float* __restrict__ qlnG, const float* __restrict__ qlnB,
                        const float* __restrict__ klnG, const float* __restrict__ klnB,
                        int l, int isLast, float* __restrict__ out) {
    int tid = threadIdx.x;                                // 256 threads
    if (blockIdx.x < 128) {
        // ======== attention: (head h, 8-row i tile) ========
        __shared__ float pqs[8][DH_];
        __shared__ float red[8][256];
        int h = blockIdx.x & 3, i0 = (blockIdx.x >> 2) * 8;
        if (isLast && blockIdx.x == 0 && tid == 0) g_pairCount = 0;   // prep next replay
        for (int idx = tid; idx < 8 * DH_; idx += 256)
            pqs[idx >> 7][idx & 127] = g_pq[(i0 + (idx >> 7)) * HD_ + h * DH_ + (idx & 127)];
        __syncthreads();
        int j = tid;
        float acc[8];
#pragma unroll
        for (int ii = 0; ii < 8; ii++) acc[ii] = 0.f;
        const float* pkt = g_pkT + h * DH_ * N_;
#pragma unroll 8
        for (int dd = 0; dd < DH_; dd++) {
            float pkv = pkt[dd * N_ + j];
#pragma unroll
            for (int ii = 0; ii < 8; ii++) acc[ii] += pqs[ii][dd] * pkv;
        }
        const float scale = 0.0883883476483184f;          // 1/sqrt(128)
        float cd = g_cdiffs[l * H_ + h];
        const float* dptr = g_diffs + (l * H_ + h) * (N_ * N_);
#pragma unroll
        for (int ii = 0; ii < 8; ii++) {
            int pr = (i0 + ii) * N_ + j;
            float dv = g_act[pr] ? dptr[pr] : cd;
            red[ii][j] = acc[ii] * scale + dv;
        }
        __syncthreads();
        // warp w owns row i0+w
        int w = tid >> 5, lane = tid & 31;
        float a[8];
#pragma unroll
        for (int k = 0; k < 8; k++) a[k] = red[w][k * 32 + lane];
        float mx = a[0];
#pragma unroll
        for (int k = 1; k < 8; k++) mx = fmaxf(mx, a[k]);
#pragma unroll
        for (int s = 16; s > 0; s >>= 1) mx = fmaxf(mx, __shfl_xor_sync(0xFFFFFFFFu, mx, s));
        float e[8], ssum = 0.f;
#pragma unroll
        for (int k = 0; k < 8; k++) { e[k] = expf(a[k] - mx); ssum += e[k]; }
#pragma unroll
        for (int s = 16; s > 0; s >>= 1) ssum += __shfl_xor_sync(0xFFFFFFFFu, ssum, s);
        int i = i0 + w;
        float predPrev;
        if (l == 0) predPrev = g_pred0[i];
        else {
            int pb = (l & 1) ^ 1;
            predPrev = 0.25f * (g_vals[pb][0][i] + g_vals[pb][1][i] +
                                g_vals[pb][2][i] + g_vals[pb][3][i]);
        }
        float vs = 0.f;
#pragma unroll
        for (int k = 0; k < 8; k++) {
            int jj = k * 32 + lane;
            float v = (jj == i) ? predPrev : nt[jj];
            vs += e[k] * v;
        }
#pragma unroll
        for (int s = 16; s > 0; s >>= 1) vs += __shfl_xor_sync(0xFFFFFFFFu, vs, s);
        if (lane == 0) {
            float r = vs / ssum;
            if (isLast) atomicAdd(&out[i], 0.25f * r);
            else        g_vals[l & 1][h][i] = r;
        }
    } else {
        // ======== residual + mish + LayerNorm for q/k, 4 rows per block ========
        __shared__ float sp[4][HD_];
        __shared__ float srs[4][64];
        __shared__ float srq[4][64];
        int ub = blockIdx.x - 128;
        bool isK = (ub >= 64);
        int r0 = (ub & 63) * 4;
        const float* P  = isK ? g_pk : g_pq;
        const float* W  = (isK ? koW : qoW) + l * HD_ * D_;
        const float* Bi = (isK ? koB : qoB) + l * D_;
        const float* G  = (isK ? klnG : qlnG) + l * D_;
        const float* Bt = (isK ? klnB : qlnB) + l * D_;
        float* dst = isK ? g_k : g_q;
        for (int idx = tid; idx < 4 * HD_; idx += 256)
            sp[idx >> 9][idx & 511] = P[(r0 + (idx >> 9)) * HD_ + (idx & 511)];
        __syncthreads();
        int r = tid >> 6, c = tid & 63;
        float acc = 0.f;
#pragma unroll 8
        for (int m = 0; m < HD_; m++) {
            float pv = sp[r][(m & 3) * DH_ + (m >> 2)];   // pq_flat[m] = pq[(m%H)*DH + m/H]
            acc += pv * W[m * D_ + c];
        }
        float y = dst[(r0 + r) * D_ + c] + mishf(acc + Bi[c]);
        srs[r][c] = y;
        srq[r][c] = y * y;
        __syncthreads();
        for (int s = 32; s > 0; s >>= 1) {
            if (c < s) { srs[r][c] += srs[r][c + s]; srq[r][c] += srq[r][c + s]; }
            __syncthreads();
        }
        float mean = srs[r][0] * (1.0f / 64.0f);
        float var  = srq[r][0] * (1.0f / 64.0f) - mean * mean;
        float o    = (y - mean) * rsqrtf(var + EPS_) * G[c] + Bt[c];
        dst[(r0 + r) * D_ + c] = o;
    }
}

// ---------------- launch ----------------
extern "C" void kernel_launch(void* const* d_in, const int* in_sizes, int n_in,
                              void* d_out, int out_size) {
    const float* X     = (const float*)d_in[0];
    const float* E     = (const float*)d_in[1];
    const float* nt    = (const float*)d_in[2];
    const float* embW  = (const float*)d_in[3];
    const float* embB  = (const float*)d_in[4];
    const float* boutW = (const float*)d_in[5];
    const float* boutB = (const float*)d_in[6];
    const float* qpW   = (const float*)d_in[7];
    const float* qpB   = (const float*)d_in[8];
    const float* kpW   = (const float*)d_in[9];
    const float* kpB   = (const float*)d_in[10];
    const float* qoW   = (const float*)d_in[11];
    const float* qoB   = (const float*)d_in[12];
    const float* koW   = (const float*)d_in[13];
    const float* koB   = (const float*)d_in[14];
    const float* bpW   = (const float*)d_in[15];
    const float* bpB   = (const float*)d_in[16];
    const float* bowW  = (const float*)d_in[17];
    const float* bowB  = (const float*)d_in[18];
    const float* qlnG  = (const float*)d_in[19];
    const float* qlnB  = (const float*)d_in[20];
    const float* klnG  = (const float*)d_in[21];
    const float* klnB  = (const float*)d_in[22];
    float* out = (float*)d_out;

    k_initdist<<<N_, 256>>>(X, E, embW, embB, boutW, boutB, out);
    k_active<<<64, 512>>>(bpW, bpB, bowW, bowB);
    for (int l = 0; l < L_; l++) {
        int isLast = (l == L_ - 1);
        k_proj<<<128, 512>>>(qpW, qpB, kpW, kpB, l);
        k_layer<<<isLast ? 128 : 256, 256>>>(nt, qoW, qoB, koW, koB,
                                             qlnG, qlnB, klnG, klnB, l, isLast, out);
    }
}